// round 1
// baseline (speedup 1.0000x reference)
#include <cuda_runtime.h>

// Problem constants
#define BB   128
#define TT   500
#define NIN  784
#define HH   1024
#define NS   102                       // n_slice = 1024/10
#define DECAY 0.8807970779778823f      // sigmoid(2.0)

// Scratch: precomputed input currents C = X @ fc1  -> [B*T, H]  (262 MB)
__device__ float g_C[(size_t)BB * TT * HH];
__device__ float g_mem[BB * HH];
__device__ float g_spk[2][BB * HH];

// ---------------------------------------------------------------------------
// init: zero state, fill tail of out (reference returns (outs, T))
// ---------------------------------------------------------------------------
__global__ void init_kernel(float* __restrict__ out, int out_size) {
    int i = blockIdx.x * blockDim.x + threadIdx.x;
    if (i < BB * HH) {
        g_mem[i] = 0.0f;
        g_spk[0][i] = 0.0f;
        g_spk[1][i] = 0.0f;
    }
    int tail = out_size - BB * TT * NS;
    if (tail > 0 && i < tail) out[BB * TT * NS + i] = 500.0f;  // T as float
}

// ---------------------------------------------------------------------------
// Phase 1: C[m, h] = sum_k X[m, k] * W[k, h]
// M = B*T = 64000, K = 784, N = 1024.  128x128 tile, BK=16, 256 thr, 8x8/thr.
// ---------------------------------------------------------------------------
__global__ void gemm_kernel(const float* __restrict__ X,
                            const float* __restrict__ W) {
    __shared__ float As[16][128];   // transposed: As[k][m]
    __shared__ float Bs[16][128];   // Bs[k][n]

    const int tid = threadIdx.x;
    const int m0 = blockIdx.y * 128;
    const int n0 = blockIdx.x * 128;
    const int tx = tid & 15;        // n micro-tile
    const int ty = tid >> 4;        // m micro-tile

    const int arow  = tid >> 2;         // 0..63
    const int akoff = (tid & 3) * 4;    // 0,4,8,12
    const int brow  = tid >> 5;         // 0..7
    const int bcol  = (tid & 31) * 4;   // 0..124

    float acc[8][8];
#pragma unroll
    for (int i = 0; i < 8; i++)
#pragma unroll
        for (int j = 0; j < 8; j++) acc[i][j] = 0.0f;

    for (int k0 = 0; k0 < NIN; k0 += 16) {
        float4 a0 = *(const float4*)&X[(size_t)(m0 + arow) * NIN + k0 + akoff];
        float4 a1 = *(const float4*)&X[(size_t)(m0 + arow + 64) * NIN + k0 + akoff];
        float4 b0 = *(const float4*)&W[(size_t)(k0 + brow) * HH + n0 + bcol];
        float4 b1 = *(const float4*)&W[(size_t)(k0 + brow + 8) * HH + n0 + bcol];

        __syncthreads();
        As[akoff + 0][arow] = a0.x;  As[akoff + 1][arow] = a0.y;
        As[akoff + 2][arow] = a0.z;  As[akoff + 3][arow] = a0.w;
        As[akoff + 0][arow + 64] = a1.x;  As[akoff + 1][arow + 64] = a1.y;
        As[akoff + 2][arow + 64] = a1.z;  As[akoff + 3][arow + 64] = a1.w;
        *(float4*)&Bs[brow][bcol]     = b0;
        *(float4*)&Bs[brow + 8][bcol] = b1;
        __syncthreads();

#pragma unroll
        for (int kk = 0; kk < 16; kk++) {
            float4 av0 = *(const float4*)&As[kk][ty * 8];
            float4 av1 = *(const float4*)&As[kk][ty * 8 + 4];
            float4 bv0 = *(const float4*)&Bs[kk][tx * 8];
            float4 bv1 = *(const float4*)&Bs[kk][tx * 8 + 4];
            float a[8] = {av0.x, av0.y, av0.z, av0.w, av1.x, av1.y, av1.z, av1.w};
            float b[8] = {bv0.x, bv0.y, bv0.z, bv0.w, bv1.x, bv1.y, bv1.z, bv1.w};
#pragma unroll
            for (int i = 0; i < 8; i++)
#pragma unroll
                for (int j = 0; j < 8; j++)
                    acc[i][j] = fmaf(a[i], b[j], acc[i][j]);
        }
    }

#pragma unroll
    for (int i = 0; i < 8; i++) {
        size_t row = (size_t)(m0 + ty * 8 + i) * HH + n0 + tx * 8;
        *(float4*)&g_C[row]     = make_float4(acc[i][0], acc[i][1], acc[i][2], acc[i][3]);
        *(float4*)&g_C[row + 4] = make_float4(acc[i][4], acc[i][5], acc[i][6], acc[i][7]);
    }
}

// ---------------------------------------------------------------------------
// Phase 2 (per step t): cur = C[:,t,:] + spk_prev @ R; LIF update; emit spikes.
// Grid: 128 blocks = 8 h-tiles(128) x 16 b-tiles(8). 128 threads.
// ---------------------------------------------------------------------------
__global__ void step_kernel(const float* __restrict__ R,
                            float* __restrict__ out, int t, int par) {
    __shared__ float s_spk[HH][8];   // [j][i] transposed, 32 KB

    const float* __restrict__ spk_in  = g_spk[par];
    float* __restrict__ spk_out = g_spk[par ^ 1];

    const int tx = threadIdx.x;                    // 0..127
    const int hx = (blockIdx.x & 7) * 128 + tx;    // hidden column
    const int b0 = (blockIdx.x >> 3) * 8;          // batch tile base

#pragma unroll
    for (int i = 0; i < 8; i++)
        for (int j = tx; j < HH; j += 128)
            s_spk[j][i] = spk_in[(b0 + i) * HH + j];
    __syncthreads();

    float acc[8];
#pragma unroll
    for (int i = 0; i < 8; i++)
        acc[i] = g_C[((size_t)(b0 + i) * TT + t) * HH + hx];

#pragma unroll 4
    for (int j = 0; j < HH; j++) {
        float r = R[(size_t)j * HH + hx];
        float4 s0 = *(const float4*)&s_spk[j][0];
        float4 s1 = *(const float4*)&s_spk[j][4];
        acc[0] = fmaf(r, s0.x, acc[0]);
        acc[1] = fmaf(r, s0.y, acc[1]);
        acc[2] = fmaf(r, s0.z, acc[2]);
        acc[3] = fmaf(r, s0.w, acc[3]);
        acc[4] = fmaf(r, s1.x, acc[4]);
        acc[5] = fmaf(r, s1.y, acc[5]);
        acc[6] = fmaf(r, s1.z, acc[6]);
        acc[7] = fmaf(r, s1.w, acc[7]);
    }

#pragma unroll
    for (int i = 0; i < 8; i++) {
        int idx = (b0 + i) * HH + hx;
        float so = spk_in[idx];
        float m  = g_mem[idx];
        // match JAX: (mem * decay) * (1 - spk) + cur, with separate roundings
        float m2 = __fadd_rn(__fmul_rn(__fmul_rn(m, DECAY), 1.0f - so), acc[i]);
        float sn = (m2 >= 1.0f) ? 1.0f : 0.0f;
        g_mem[idx]   = m2;
        spk_out[idx] = sn;
        if (hx < NS)
            out[((size_t)(b0 + i) * TT + t) * NS + hx] = sn;
    }
}

// ---------------------------------------------------------------------------
extern "C" void kernel_launch(void* const* d_in, const int* in_sizes, int n_in,
                              void* d_out, int out_size) {
    const float* x   = (const float*)d_in[0];   // [B, T, NIN]
    const float* fc1 = (const float*)d_in[1];   // [NIN, H]
    const float* rec = (const float*)d_in[2];   // [H, H]
    float* out = (float*)d_out;

    init_kernel<<<(BB * HH + 255) / 256, 256>>>(out, out_size);
    gemm_kernel<<<dim3(HH / 128, (BB * TT) / 128), 256>>>(x, fc1);
    for (int t = 0; t < TT; t++)
        step_kernel<<<128, 128>>>(rec, out, t, t & 1);
}

// round 2
// speedup vs baseline: 4.4862x; 4.4862x over previous
#include <cuda_runtime.h>

// Problem constants
#define BB   128
#define TT   500
#define NIN  784
#define HH   1024
#define NS   102                       // n_slice = 1024/10
#define DECAY 0.8807970779778823f      // sigmoid(2.0)

// Persistent-kernel decomposition
#define NBLK 256
#define NTHR 256
#define NJT  16          // j tiles
#define JT   64          // j per tile
#define NHT  4           // h tiles
#define HT   256         // h per tile
#define NBG  4           // batch groups of 32
#define SPST 36          // spk smem row stride (pad, 16B-aligned)

// Scratch
__device__ float g_C[(size_t)BB * TT * HH];      // X @ fc1 precomputed  (262 MB)
__device__ float g_part[NJT][BB][HH];            // per-j-tile partial sums (8 MB)
__device__ float g_spk1[BB * HH];                // spike state
__device__ unsigned g_bar_cnt;
__device__ volatile unsigned g_bar_gen;

// ---------------------------------------------------------------------------
__global__ void init_kernel(float* __restrict__ out, int out_size) {
    int i = blockIdx.x * blockDim.x + threadIdx.x;
    if (i < BB * HH) g_spk1[i] = 0.0f;
    int tail = out_size - BB * TT * NS;
    if (tail > 0 && i < tail) out[BB * TT * NS + i] = 500.0f;  // returned T
}

// ---------------------------------------------------------------------------
// Phase 1: C = X @ fc1.  M=64000, K=784, N=1024. 128x128 tile, BK=16.
// ---------------------------------------------------------------------------
__global__ void gemm_kernel(const float* __restrict__ X,
                            const float* __restrict__ W) {
    __shared__ float As[16][128];
    __shared__ float Bs[16][128];

    const int tid = threadIdx.x;
    const int m0 = blockIdx.y * 128;
    const int n0 = blockIdx.x * 128;
    const int tx = tid & 15;
    const int ty = tid >> 4;

    const int arow  = tid >> 2;
    const int akoff = (tid & 3) * 4;
    const int brow  = tid >> 5;
    const int bcol  = (tid & 31) * 4;

    float acc[8][8];
#pragma unroll
    for (int i = 0; i < 8; i++)
#pragma unroll
        for (int j = 0; j < 8; j++) acc[i][j] = 0.0f;

    for (int k0 = 0; k0 < NIN; k0 += 16) {
        float4 a0 = *(const float4*)&X[(size_t)(m0 + arow) * NIN + k0 + akoff];
        float4 a1 = *(const float4*)&X[(size_t)(m0 + arow + 64) * NIN + k0 + akoff];
        float4 b0 = *(const float4*)&W[(size_t)(k0 + brow) * HH + n0 + bcol];
        float4 b1 = *(const float4*)&W[(size_t)(k0 + brow + 8) * HH + n0 + bcol];

        __syncthreads();
        As[akoff + 0][arow] = a0.x;  As[akoff + 1][arow] = a0.y;
        As[akoff + 2][arow] = a0.z;  As[akoff + 3][arow] = a0.w;
        As[akoff + 0][arow + 64] = a1.x;  As[akoff + 1][arow + 64] = a1.y;
        As[akoff + 2][arow + 64] = a1.z;  As[akoff + 3][arow + 64] = a1.w;
        *(float4*)&Bs[brow][bcol]     = b0;
        *(float4*)&Bs[brow + 8][bcol] = b1;
        __syncthreads();

#pragma unroll
        for (int kk = 0; kk < 16; kk++) {
            float4 av0 = *(const float4*)&As[kk][ty * 8];
            float4 av1 = *(const float4*)&As[kk][ty * 8 + 4];
            float4 bv0 = *(const float4*)&Bs[kk][tx * 8];
            float4 bv1 = *(const float4*)&Bs[kk][tx * 8 + 4];
            float a[8] = {av0.x, av0.y, av0.z, av0.w, av1.x, av1.y, av1.z, av1.w};
            float b[8] = {bv0.x, bv0.y, bv0.z, bv0.w, bv1.x, bv1.y, bv1.z, bv1.w};
#pragma unroll
            for (int i = 0; i < 8; i++)
#pragma unroll
                for (int j = 0; j < 8; j++)
                    acc[i][j] = fmaf(a[i], b[j], acc[i][j]);
        }
    }

#pragma unroll
    for (int i = 0; i < 8; i++) {
        size_t row = (size_t)(m0 + ty * 8 + i) * HH + n0 + tx * 8;
        *(float4*)&g_C[row]     = make_float4(acc[i][0], acc[i][1], acc[i][2], acc[i][3]);
        *(float4*)&g_C[row + 4] = make_float4(acc[i][4], acc[i][5], acc[i][6], acc[i][7]);
    }
}

// ---------------------------------------------------------------------------
// Software grid barrier (all NBLK blocks are co-resident by construction).
// ---------------------------------------------------------------------------
__device__ __forceinline__ void grid_sync() {
    __threadfence();          // release: make this block's stores visible
    __syncthreads();
    if (threadIdx.x == 0) {
        unsigned gen = g_bar_gen;
        if (atomicAdd(&g_bar_cnt, 1u) == NBLK - 1) {
            g_bar_cnt = 0;
            __threadfence();
            g_bar_gen = gen + 1;
        } else {
            while (g_bar_gen == gen) __nanosleep(40);
        }
        __threadfence();      // acquire: invalidate L1 before consuming
    }
    __syncthreads();
}

// ---------------------------------------------------------------------------
// Persistent recurrent kernel: all 500 steps, 2 grid barriers per step.
// Block (bg, ht, jt): holds R[j0:j0+64, h0:h0+256] in smem for the whole run.
// Phase A: partial[b0:b0+32, h0:h0+256] += spk[b, j-range] @ Rslice
// Phase B: each thread LIFs 2 owned (b,h) elements; mem & prev-spike in regs.
// ---------------------------------------------------------------------------
__global__ void __launch_bounds__(NTHR, 2)
rsnn_persistent(const float* __restrict__ R, float* __restrict__ out) {
    extern __shared__ float sm[];
    float* Rs = sm;                    // [JT][HT]
    float* Sp = sm + JT * HT;          // [JT][SPST]

    const int bid = blockIdx.x;
    const int jt = bid & 15;
    const int ht = (bid >> 4) & 3;
    const int bg = bid >> 6;
    const int j0 = jt * JT;
    const int h0 = ht * HT;
    const int b0 = bg * 32;
    const int tid = threadIdx.x;
    const int tx = tid & 31;           // h subtile: h = h0 + tx*8
    const int ty = tid >> 5;           // b subtile: b = b0 + ty*4

    // Load R slice once (reused for all 500 steps)
    for (int i = tid; i < JT * HT / 4; i += NTHR) {
        int j = i / (HT / 4);
        int h4 = i % (HT / 4);
        ((float4*)Rs)[i] = __ldg(&((const float4*)(R + (size_t)(j0 + j) * HH + h0))[h4]);
    }

    // LIF ownership: 2 consecutive-h elements per thread
    const int e0 = bid * (BB * HH / NBLK) + tid * 2;
    const int bl = e0 >> 10;
    const int hl = e0 & 1023;
    float mem0 = 0.0f, mem1 = 0.0f, s0 = 0.0f, s1 = 0.0f;

    for (int t = 0; t < TT; t++) {
        // ---- stage spikes [32 b][JT j] -> Sp[j][b] (transposed, padded) ----
        for (int i = tid; i < 32 * JT; i += NTHR) {
            int b = i >> 6;
            int j = i & 63;
            Sp[j * SPST + b] = __ldcg(&g_spk1[(b0 + b) * HH + j0 + j]);
        }
        __syncthreads();

        // ---- partial GEMM: 4b x 8h per thread over JT j ----
        float acc[4][8];
#pragma unroll
        for (int i = 0; i < 4; i++)
#pragma unroll
            for (int k = 0; k < 8; k++) acc[i][k] = 0.0f;

#pragma unroll 8
        for (int j = 0; j < JT; j++) {
            float4 s4 = *(const float4*)&Sp[j * SPST + ty * 4];
            float4 r0 = *(const float4*)&Rs[j * HT + tx * 8];
            float4 r1 = *(const float4*)&Rs[j * HT + tx * 8 + 4];
            float sv[4] = {s4.x, s4.y, s4.z, s4.w};
            float rv[8] = {r0.x, r0.y, r0.z, r0.w, r1.x, r1.y, r1.z, r1.w};
#pragma unroll
            for (int i = 0; i < 4; i++)
#pragma unroll
                for (int k = 0; k < 8; k++)
                    acc[i][k] = fmaf(sv[i], rv[k], acc[i][k]);
        }

#pragma unroll
        for (int i = 0; i < 4; i++) {
            float* p = &g_part[jt][b0 + ty * 4 + i][h0 + tx * 8];
            *(float4*)p       = make_float4(acc[i][0], acc[i][1], acc[i][2], acc[i][3]);
            *(float4*)(p + 4) = make_float4(acc[i][4], acc[i][5], acc[i][6], acc[i][7]);
        }
        grid_sync();
        __syncthreads();   // Sp reuse protection before next stage (cheap)

        // ---- LIF phase: 2 owned elements ----
        float2 cur = *(const float2*)&g_C[((size_t)bl * TT + t) * HH + hl];
#pragma unroll
        for (int q = 0; q < NJT; q++) {
            float2 pv = __ldcg((const float2*)&g_part[q][bl][hl]);
            cur.x += pv.x;
            cur.y += pv.y;
        }
        // match JAX rounding: ((mem * decay) * (1 - spk)) + cur
        mem0 = __fadd_rn(__fmul_rn(__fmul_rn(mem0, DECAY), 1.0f - s0), cur.x);
        mem1 = __fadd_rn(__fmul_rn(__fmul_rn(mem1, DECAY), 1.0f - s1), cur.y);
        s0 = (mem0 >= 1.0f) ? 1.0f : 0.0f;
        s1 = (mem1 >= 1.0f) ? 1.0f : 0.0f;
        *(float2*)&g_spk1[bl * HH + hl] = make_float2(s0, s1);
        if (hl < NS)
            *(float2*)&out[((size_t)bl * TT + t) * NS + hl] = make_float2(s0, s1);
        grid_sync();
    }
}

// ---------------------------------------------------------------------------
extern "C" void kernel_launch(void* const* d_in, const int* in_sizes, int n_in,
                              void* d_out, int out_size) {
    const float* x   = (const float*)d_in[0];   // [B, T, NIN]
    const float* fc1 = (const float*)d_in[1];   // [NIN, H]
    const float* rec = (const float*)d_in[2];   // [H, H]
    float* out = (float*)d_out;

    const int smem = (JT * HT + JT * SPST) * sizeof(float);  // ~73.7 KB
    cudaFuncSetAttribute(rsnn_persistent,
                         cudaFuncAttributeMaxDynamicSharedMemorySize, smem);

    init_kernel<<<(BB * HH + 255) / 256, 256>>>(out, out_size);
    gemm_kernel<<<dim3(HH / 128, (BB * TT) / 128), 256>>>(x, fc1);
    rsnn_persistent<<<NBLK, NTHR, smem>>>(rec, out);
}

// round 4
// speedup vs baseline: 4.5364x; 1.0112x over previous
#include <cuda_runtime.h>
#include <cuda_bf16.h>
#include <cstdint>

// Problem constants
#define BB   128
#define TT   500
#define NIN  784
#define HH   1024
#define NS   102
#define DECAY 0.8807970779778823f      // sigmoid(2.0)
#define KP   832                       // NIN padded (multiple of 32)
#define KC   32                        // gemm K-chunk
#define NCH  (KP / KC)                 // 26 chunks
#define TSTRIDE 80                     // smem row stride (bytes): 64B data + 16B pad

// Persistent-kernel decomposition
#define NBLK 256
#define NTHR 256
#define NJT  16
#define JT   64
#define HT   256
#define SPST 36

// Scratch
__device__ float g_C[(size_t)BB * TT * HH];              // X @ fc1  (262 MB)
__device__ float g_part[NJT][BB][HH];                    // partial sums (8 MB)
__device__ float g_spk1[BB * HH];
__device__ unsigned g_bar_cnt;
__device__ volatile unsigned g_bar_gen;
__device__ __nv_bfloat16 g_Xs[3][(size_t)BB * TT * KP];  // X splits (320 MB)
__device__ __nv_bfloat16 g_Wt[3][(size_t)HH * KP];       // W^T splits (5 MB)

__device__ __forceinline__ uint32_t smem_u32(const void* p) {
    uint32_t a;
    asm("{ .reg .u64 t; cvta.to.shared.u64 t, %1; cvt.u32.u64 %0, t; }" : "=r"(a) : "l"(p));
    return a;
}

// ---------------------------------------------------------------------------
__global__ void init_kernel(float* __restrict__ out, int out_size) {
    int i = blockIdx.x * blockDim.x + threadIdx.x;
    if (i < BB * HH) g_spk1[i] = 0.0f;
    int tail = out_size - BB * TT * NS;
    if (tail > 0 && i < tail) out[BB * TT * NS + i] = 500.0f;
}

// ---------------------------------------------------------------------------
// Exact 3-term bf16 splits (hi/mid/lo), K padded to KP.
// ---------------------------------------------------------------------------
__global__ void split_x_kernel(const float* __restrict__ X) {
    int i = blockIdx.x * blockDim.x + threadIdx.x;
    if (i >= BB * TT * (KP / 2)) return;
    int m  = i / (KP / 2);
    int k  = (i % (KP / 2)) * 2;
    float v0 = 0.f, v1 = 0.f;
    if (k < NIN) { v0 = X[(size_t)m * NIN + k]; v1 = X[(size_t)m * NIN + k + 1]; }
    __nv_bfloat16 a1 = __float2bfloat16_rn(v0);
    float r = v0 - __bfloat162float(a1);
    __nv_bfloat16 a2 = __float2bfloat16_rn(r);
    __nv_bfloat16 a3 = __float2bfloat16_rn(r - __bfloat162float(a2));
    __nv_bfloat16 b1 = __float2bfloat16_rn(v1);
    float r2 = v1 - __bfloat162float(b1);
    __nv_bfloat16 b2 = __float2bfloat16_rn(r2);
    __nv_bfloat16 b3 = __float2bfloat16_rn(r2 - __bfloat162float(b2));
    size_t o = (size_t)m * KP + k;
    *(__nv_bfloat162*)&g_Xs[0][o] = __nv_bfloat162(a1, b1);
    *(__nv_bfloat162*)&g_Xs[1][o] = __nv_bfloat162(a2, b2);
    *(__nv_bfloat162*)&g_Xs[2][o] = __nv_bfloat162(a3, b3);
}

__global__ void split_w_kernel(const float* __restrict__ W) {
    int i = blockIdx.x * blockDim.x + threadIdx.x;
    if (i >= HH * (KP / 2)) return;
    int n = i / (KP / 2);
    int k = (i % (KP / 2)) * 2;
    float v0 = (k < NIN)     ? W[(size_t)k * HH + n]       : 0.f;
    float v1 = (k + 1 < NIN) ? W[(size_t)(k + 1) * HH + n] : 0.f;
    __nv_bfloat16 a1 = __float2bfloat16_rn(v0);
    float r = v0 - __bfloat162float(a1);
    __nv_bfloat16 a2 = __float2bfloat16_rn(r);
    __nv_bfloat16 a3 = __float2bfloat16_rn(r - __bfloat162float(a2));
    __nv_bfloat16 b1 = __float2bfloat16_rn(v1);
    float r2 = v1 - __bfloat162float(b1);
    __nv_bfloat16 b2 = __float2bfloat16_rn(r2);
    __nv_bfloat16 b3 = __float2bfloat16_rn(r2 - __bfloat162float(b2));
    size_t o = (size_t)n * KP + k;
    *(__nv_bfloat162*)&g_Wt[0][o] = __nv_bfloat162(a1, b1);
    *(__nv_bfloat162*)&g_Wt[1][o] = __nv_bfloat162(a2, b2);
    *(__nv_bfloat162*)&g_Wt[2][o] = __nv_bfloat162(a3, b3);
}

// ---------------------------------------------------------------------------
// Phase 1 via warp-level mma.sync (baseline PTX, works on compute_103):
// C tile 128x128, 8 warps (2m x 4n), warp tile 64x32, K-chunk 32, 6 products.
// ---------------------------------------------------------------------------
__global__ void __launch_bounds__(256, 2)
gemm_tc_kernel() {
    extern __shared__ char dynsm[];
    const uint32_t smb = smem_u32(dynsm);

    const int tid = threadIdx.x;
    const int wid = tid >> 5;
    const int lane = tid & 31;
    const int n0 = (blockIdx.x & 7) * 128;
    const int m0 = (blockIdx.x >> 3) * 128;
    const int wm = (wid & 1) * 64;       // warp m base within tile
    const int wn = (wid >> 1) * 32;      // warp n base within tile

    float acc[4][4][4];                   // [mf][nf][c0..c3]
#pragma unroll
    for (int a = 0; a < 4; a++)
#pragma unroll
        for (int b = 0; b < 4; b++)
#pragma unroll
            for (int c = 0; c < 4; c++) acc[a][b][c] = 0.0f;

    const int pa[6] = {0, 0, 1, 1, 0, 2};
    const int pb[6] = {0, 1, 0, 1, 2, 0};

    // precomputed ldmatrix lane addresses (byte offsets within a tile)
    const uint32_t a_off = (uint32_t)(lane & 15) * TSTRIDE + ((lane >> 4) << 4);
    const uint32_t b_off = (uint32_t)((lane & 7) + ((lane >> 4) << 3)) * TSTRIDE +
                           (((lane >> 3) & 1) << 4);

    for (int c = 0; c < NCH; c++) {
        __syncthreads();
        // stage 6 tiles: [128 rows][32 k] bf16, row stride 80B
        for (int i = tid; i < 3072; i += 256) {
            int tile = i >> 9;           // 0..5
            int r = i & 511;
            int row = r >> 2, seg = r & 3;
            uint4 v;
            if (tile < 3)
                v = ((const uint4*)g_Xs[tile])[(size_t)(m0 + row) * (KP / 8) + c * 4 + seg];
            else
                v = ((const uint4*)g_Wt[tile - 3])[(size_t)(n0 + row) * (KP / 8) + c * 4 + seg];
            uint32_t dst = smb + tile * (128 * TSTRIDE) + row * TSTRIDE + seg * 16;
            asm volatile("st.shared.v4.b32 [%0], {%1,%2,%3,%4};"
                         :: "r"(dst), "r"(v.x), "r"(v.y), "r"(v.z), "r"(v.w) : "memory");
        }
        __syncthreads();

#pragma unroll
        for (int q = 0; q < 6; q++) {
            uint32_t Ab = smb + pa[q] * (128 * TSTRIDE);
            uint32_t Bb = smb + (3 + pb[q]) * (128 * TSTRIDE);
#pragma unroll
            for (int ks = 0; ks < 2; ks++) {
                // B fragments: two x4 loads cover n 0..31 for this k-step
                uint32_t b0[4], b1[4];
                asm volatile("ldmatrix.sync.aligned.m8n8.x4.shared.b16 {%0,%1,%2,%3}, [%4];"
                             : "=r"(b0[0]), "=r"(b0[1]), "=r"(b0[2]), "=r"(b0[3])
                             : "r"(Bb + (wn + 0) * TSTRIDE + b_off + ks * 32));
                asm volatile("ldmatrix.sync.aligned.m8n8.x4.shared.b16 {%0,%1,%2,%3}, [%4];"
                             : "=r"(b1[0]), "=r"(b1[1]), "=r"(b1[2]), "=r"(b1[3])
                             : "r"(Bb + (wn + 16) * TSTRIDE + b_off + ks * 32));
#pragma unroll
                for (int mf = 0; mf < 4; mf++) {
                    uint32_t a[4];
                    asm volatile("ldmatrix.sync.aligned.m8n8.x4.shared.b16 {%0,%1,%2,%3}, [%4];"
                                 : "=r"(a[0]), "=r"(a[1]), "=r"(a[2]), "=r"(a[3])
                                 : "r"(Ab + (wm + mf * 16) * TSTRIDE + a_off + ks * 32));
#pragma unroll
                    for (int nf = 0; nf < 4; nf++) {
                        uint32_t* bp = (nf < 2) ? &b0[(nf & 1) * 2] : &b1[(nf & 1) * 2];
                        asm volatile(
                            "mma.sync.aligned.m16n8k16.row.col.f32.bf16.bf16.f32 "
                            "{%0,%1,%2,%3}, {%4,%5,%6,%7}, {%8,%9}, {%0,%1,%2,%3};"
                            : "+f"(acc[mf][nf][0]), "+f"(acc[mf][nf][1]),
                              "+f"(acc[mf][nf][2]), "+f"(acc[mf][nf][3])
                            : "r"(a[0]), "r"(a[1]), "r"(a[2]), "r"(a[3]),
                              "r"(bp[0]), "r"(bp[1]));
                    }
                }
            }
        }
    }

    // epilogue: c0,c1 -> (row g, col 2c), c2,c3 -> (row g+8)
    const int mrow = m0 + wm + (lane >> 2);
    const int ncol = n0 + wn + (lane & 3) * 2;
#pragma unroll
    for (int mf = 0; mf < 4; mf++)
#pragma unroll
        for (int nf = 0; nf < 4; nf++) {
            size_t base = (size_t)(mrow + mf * 16) * HH + ncol + nf * 8;
            *(float2*)&g_C[base]          = make_float2(acc[mf][nf][0], acc[mf][nf][1]);
            *(float2*)&g_C[base + 8 * HH] = make_float2(acc[mf][nf][2], acc[mf][nf][3]);
        }
}

// ---------------------------------------------------------------------------
// Software grid barrier (all NBLK blocks co-resident).
// ---------------------------------------------------------------------------
__device__ __forceinline__ void grid_sync() {
    __threadfence();
    __syncthreads();
    if (threadIdx.x == 0) {
        unsigned gen = g_bar_gen;
        if (atomicAdd(&g_bar_cnt, 1u) == NBLK - 1) {
            g_bar_cnt = 0;
            __threadfence();
            g_bar_gen = gen + 1;
        } else {
            while (g_bar_gen == gen) __nanosleep(40);
        }
        __threadfence();
    }
    __syncthreads();
}

// ---------------------------------------------------------------------------
// Persistent recurrent kernel: 500 steps, 2 grid barriers per step.
// ---------------------------------------------------------------------------
__global__ void __launch_bounds__(NTHR, 2)
rsnn_persistent(const float* __restrict__ R, float* __restrict__ out) {
    extern __shared__ float sm[];
    float* Rs = sm;                    // [JT][HT]
    float* Sp = sm + JT * HT;          // [JT][SPST]

    const int bid = blockIdx.x;
    const int jt = bid & 15;
    const int ht = (bid >> 4) & 3;
    const int bg = bid >> 6;
    const int j0 = jt * JT;
    const int h0 = ht * HT;
    const int b0 = bg * 32;
    const int tid = threadIdx.x;
    const int tx = tid & 31;
    const int ty = tid >> 5;

    for (int i = tid; i < JT * HT / 4; i += NTHR) {
        int j = i / (HT / 4);
        int h4 = i % (HT / 4);
        ((float4*)Rs)[i] = __ldg(&((const float4*)(R + (size_t)(j0 + j) * HH + h0))[h4]);
    }

    const int e0 = bid * (BB * HH / NBLK) + tid * 2;
    const int bl = e0 >> 10;
    const int hl = e0 & 1023;
    float mem0 = 0.0f, mem1 = 0.0f, s0 = 0.0f, s1 = 0.0f;

    for (int t = 0; t < TT; t++) {
        float2 cur = *(const float2*)&g_C[((size_t)bl * TT + t) * HH + hl];

        for (int i = tid; i < 32 * JT; i += NTHR) {
            int b = i >> 6;
            int j = i & 63;
            Sp[j * SPST + b] = __ldcg(&g_spk1[(b0 + b) * HH + j0 + j]);
        }
        __syncthreads();

        float acc[4][8];
#pragma unroll
        for (int i = 0; i < 4; i++)
#pragma unroll
            for (int k = 0; k < 8; k++) acc[i][k] = 0.0f;

#pragma unroll 8
        for (int j = 0; j < JT; j++) {
            float4 s4 = *(const float4*)&Sp[j * SPST + ty * 4];
            float4 r0 = *(const float4*)&Rs[j * HT + tx * 8];
            float4 r1 = *(const float4*)&Rs[j * HT + tx * 8 + 4];
            float sv[4] = {s4.x, s4.y, s4.z, s4.w};
            float rv[8] = {r0.x, r0.y, r0.z, r0.w, r1.x, r1.y, r1.z, r1.w};
#pragma unroll
            for (int i = 0; i < 4; i++)
#pragma unroll
                for (int k = 0; k < 8; k++)
                    acc[i][k] = fmaf(sv[i], rv[k], acc[i][k]);
        }

#pragma unroll
        for (int i = 0; i < 4; i++) {
            float* p = &g_part[jt][b0 + ty * 4 + i][h0 + tx * 8];
            *(float4*)p       = make_float4(acc[i][0], acc[i][1], acc[i][2], acc[i][3]);
            *(float4*)(p + 4) = make_float4(acc[i][4], acc[i][5], acc[i][6], acc[i][7]);
        }
        grid_sync();

#pragma unroll
        for (int q = 0; q < NJT; q++) {
            float2 pv = __ldcg((const float2*)&g_part[q][bl][hl]);
            cur.x += pv.x;
            cur.y += pv.y;
        }
        mem0 = __fadd_rn(__fmul_rn(__fmul_rn(mem0, DECAY), 1.0f - s0), cur.x);
        mem1 = __fadd_rn(__fmul_rn(__fmul_rn(mem1, DECAY), 1.0f - s1), cur.y);
        s0 = (mem0 >= 1.0f) ? 1.0f : 0.0f;
        s1 = (mem1 >= 1.0f) ? 1.0f : 0.0f;
        *(float2*)&g_spk1[bl * HH + hl] = make_float2(s0, s1);
        if (hl < NS)
            *(float2*)&out[((size_t)bl * TT + t) * NS + hl] = make_float2(s0, s1);
        grid_sync();
    }
}

// ---------------------------------------------------------------------------
extern "C" void kernel_launch(void* const* d_in, const int* in_sizes, int n_in,
                              void* d_out, int out_size) {
    const float* x   = (const float*)d_in[0];
    const float* fc1 = (const float*)d_in[1];
    const float* rec = (const float*)d_in[2];
    float* out = (float*)d_out;

    const int smem_p = (JT * HT + JT * SPST) * sizeof(float);
    cudaFuncSetAttribute(rsnn_persistent,
                         cudaFuncAttributeMaxDynamicSharedMemorySize, smem_p);
    const int smem_g = 6 * 128 * TSTRIDE;   // 61,440 B
    cudaFuncSetAttribute(gemm_tc_kernel,
                         cudaFuncAttributeMaxDynamicSharedMemorySize, smem_g);

    init_kernel<<<(BB * HH + 255) / 256, 256>>>(out, out_size);
    split_x_kernel<<<(BB * TT * (KP / 2) + 255) / 256, 256>>>(x);
    split_w_kernel<<<(HH * (KP / 2) + 255) / 256, 256>>>(fc1);
    gemm_tc_kernel<<<4000, 256, smem_g>>>();
    rsnn_persistent<<<NBLK, NTHR, smem_p>>>(rec, out);
}

// round 6
// speedup vs baseline: 7.2500x; 1.5982x over previous
#include <cuda_runtime.h>
#include <cuda_bf16.h>
#include <cstdint>

// Problem constants
#define BB   128
#define TT   500
#define NIN  784
#define HH   1024
#define NS   102
#define DECAY 0.8807970779778823f      // sigmoid(2.0)
#define KP   832                       // NIN padded (multiple of 32)
#define KC   32
#define NCH  (KP / KC)
#define TSTRIDE 80                     // phase-1 smem row stride

// Persistent recurrent decomposition
#define NBLK 128
#define NTHR 256
#define NJT  4
#define JTS  256                       // j per tile
#define HTS  32                        // h per tile
#define ASTR 528                       // smem row stride bytes (512 data + 16 pad)

// Scratch
__device__ float g_C[(size_t)BB * TT * HH];              // X @ fc1  (262 MB)
__device__ float g_part[NJT][BB][HH];                    // j-partials (2 MB)
__device__ __nv_bfloat16 g_spkb[2][BB * HH];             // spike state, bf16, dbl-buf
__device__ unsigned g_bar_cnt;
__device__ volatile unsigned g_bar_gen;
__device__ __nv_bfloat16 g_Xs[3][(size_t)BB * TT * KP];  // X splits (320 MB)
__device__ __nv_bfloat16 g_Wt[3][(size_t)HH * KP];       // fc1^T splits (5 MB)
__device__ __nv_bfloat16 g_Rt[3][(size_t)HH * HH];       // R^T splits (6 MB)

__device__ __forceinline__ uint32_t smem_u32(const void* p) {
    uint32_t a;
    asm("{ .reg .u64 t; cvta.to.shared.u64 t, %1; cvt.u32.u64 %0, t; }" : "=r"(a) : "l"(p));
    return a;
}

// ---------------------------------------------------------------------------
__global__ void init_kernel(float* __restrict__ out, int out_size) {
    int i = blockIdx.x * blockDim.x + threadIdx.x;
    if (i < BB * HH) {
        g_spkb[0][i] = __float2bfloat16_rn(0.f);
        g_spkb[1][i] = __float2bfloat16_rn(0.f);
    }
    int tail = out_size - BB * TT * NS;
    if (tail > 0 && i < tail) out[BB * TT * NS + i] = 500.0f;
}

// ---------------------------------------------------------------------------
// Exact 3-term bf16 splits.
// ---------------------------------------------------------------------------
__global__ void split_x_kernel(const float* __restrict__ X) {
    int i = blockIdx.x * blockDim.x + threadIdx.x;
    if (i >= BB * TT * (KP / 2)) return;
    int m = i / (KP / 2);
    int k = (i % (KP / 2)) * 2;
    float v0 = 0.f, v1 = 0.f;
    if (k < NIN) { v0 = X[(size_t)m * NIN + k]; v1 = X[(size_t)m * NIN + k + 1]; }
    __nv_bfloat16 a1 = __float2bfloat16_rn(v0);
    float r = v0 - __bfloat162float(a1);
    __nv_bfloat16 a2 = __float2bfloat16_rn(r);
    __nv_bfloat16 a3 = __float2bfloat16_rn(r - __bfloat162float(a2));
    __nv_bfloat16 b1 = __float2bfloat16_rn(v1);
    float r2 = v1 - __bfloat162float(b1);
    __nv_bfloat16 b2 = __float2bfloat16_rn(r2);
    __nv_bfloat16 b3 = __float2bfloat16_rn(r2 - __bfloat162float(b2));
    size_t o = (size_t)m * KP + k;
    *(__nv_bfloat162*)&g_Xs[0][o] = __nv_bfloat162(a1, b1);
    *(__nv_bfloat162*)&g_Xs[1][o] = __nv_bfloat162(a2, b2);
    *(__nv_bfloat162*)&g_Xs[2][o] = __nv_bfloat162(a3, b3);
}

__global__ void split_w_kernel(const float* __restrict__ W) {
    int i = blockIdx.x * blockDim.x + threadIdx.x;
    if (i >= HH * (KP / 2)) return;
    int n = i / (KP / 2);
    int k = (i % (KP / 2)) * 2;
    float v0 = (k < NIN)     ? W[(size_t)k * HH + n]       : 0.f;
    float v1 = (k + 1 < NIN) ? W[(size_t)(k + 1) * HH + n] : 0.f;
    __nv_bfloat16 a1 = __float2bfloat16_rn(v0);
    float r = v0 - __bfloat162float(a1);
    __nv_bfloat16 a2 = __float2bfloat16_rn(r);
    __nv_bfloat16 a3 = __float2bfloat16_rn(r - __bfloat162float(a2));
    __nv_bfloat16 b1 = __float2bfloat16_rn(v1);
    float r2 = v1 - __bfloat162float(b1);
    __nv_bfloat16 b2 = __float2bfloat16_rn(r2);
    __nv_bfloat16 b3 = __float2bfloat16_rn(r2 - __bfloat162float(b2));
    size_t o = (size_t)n * KP + k;
    *(__nv_bfloat162*)&g_Wt[0][o] = __nv_bfloat162(a1, b1);
    *(__nv_bfloat162*)&g_Wt[1][o] = __nv_bfloat162(a2, b2);
    *(__nv_bfloat162*)&g_Wt[2][o] = __nv_bfloat162(a3, b3);
}

// R^T splits: g_Rt[p][h][j] = split_p(R[j][h])
__global__ void split_r_kernel(const float* __restrict__ R) {
    int i = blockIdx.x * blockDim.x + threadIdx.x;
    if (i >= HH * (HH / 2)) return;
    int h = i / (HH / 2);
    int j = (i % (HH / 2)) * 2;
    float v0 = R[(size_t)j * HH + h];
    float v1 = R[(size_t)(j + 1) * HH + h];
    __nv_bfloat16 a1 = __float2bfloat16_rn(v0);
    float r = v0 - __bfloat162float(a1);
    __nv_bfloat16 a2 = __float2bfloat16_rn(r);
    __nv_bfloat16 a3 = __float2bfloat16_rn(r - __bfloat162float(a2));
    __nv_bfloat16 b1 = __float2bfloat16_rn(v1);
    float r2 = v1 - __bfloat162float(b1);
    __nv_bfloat16 b2 = __float2bfloat16_rn(r2);
    __nv_bfloat16 b3 = __float2bfloat16_rn(r2 - __bfloat162float(b2));
    size_t o = (size_t)h * HH + j;
    *(__nv_bfloat162*)&g_Rt[0][o] = __nv_bfloat162(a1, b1);
    *(__nv_bfloat162*)&g_Rt[1][o] = __nv_bfloat162(a2, b2);
    *(__nv_bfloat162*)&g_Rt[2][o] = __nv_bfloat162(a3, b3);
}

// ---------------------------------------------------------------------------
// Phase 1 via warp-level mma.sync (unchanged from round 4, passed rel_err 0).
// ---------------------------------------------------------------------------
__global__ void __launch_bounds__(256, 2)
gemm_tc_kernel() {
    extern __shared__ char dynsm[];
    const uint32_t smb = smem_u32(dynsm);

    const int tid = threadIdx.x;
    const int wid = tid >> 5;
    const int lane = tid & 31;
    const int n0 = (blockIdx.x & 7) * 128;
    const int m0 = (blockIdx.x >> 3) * 128;
    const int wm = (wid & 1) * 64;
    const int wn = (wid >> 1) * 32;

    float acc[4][4][4];
#pragma unroll
    for (int a = 0; a < 4; a++)
#pragma unroll
        for (int b = 0; b < 4; b++)
#pragma unroll
            for (int c = 0; c < 4; c++) acc[a][b][c] = 0.0f;

    const int pa[6] = {0, 0, 1, 1, 0, 2};
    const int pb[6] = {0, 1, 0, 1, 2, 0};

    const uint32_t a_off = (uint32_t)(lane & 15) * TSTRIDE + ((lane >> 4) << 4);
    const uint32_t b_off = (uint32_t)((lane & 7) + ((lane >> 4) << 3)) * TSTRIDE +
                           (((lane >> 3) & 1) << 4);

    for (int c = 0; c < NCH; c++) {
        __syncthreads();
        for (int i = tid; i < 3072; i += 256) {
            int tile = i >> 9;
            int r = i & 511;
            int row = r >> 2, seg = r & 3;
            uint4 v;
            if (tile < 3)
                v = ((const uint4*)g_Xs[tile])[(size_t)(m0 + row) * (KP / 8) + c * 4 + seg];
            else
                v = ((const uint4*)g_Wt[tile - 3])[(size_t)(n0 + row) * (KP / 8) + c * 4 + seg];
            uint32_t dst = smb + tile * (128 * TSTRIDE) + row * TSTRIDE + seg * 16;
            asm volatile("st.shared.v4.b32 [%0], {%1,%2,%3,%4};"
                         :: "r"(dst), "r"(v.x), "r"(v.y), "r"(v.z), "r"(v.w) : "memory");
        }
        __syncthreads();

#pragma unroll
        for (int q = 0; q < 6; q++) {
            uint32_t Ab = smb + pa[q] * (128 * TSTRIDE);
            uint32_t Bb = smb + (3 + pb[q]) * (128 * TSTRIDE);
#pragma unroll
            for (int ks = 0; ks < 2; ks++) {
                uint32_t b0[4], b1[4];
                asm volatile("ldmatrix.sync.aligned.m8n8.x4.shared.b16 {%0,%1,%2,%3}, [%4];"
                             : "=r"(b0[0]), "=r"(b0[1]), "=r"(b0[2]), "=r"(b0[3])
                             : "r"(Bb + (wn + 0) * TSTRIDE + b_off + ks * 32));
                asm volatile("ldmatrix.sync.aligned.m8n8.x4.shared.b16 {%0,%1,%2,%3}, [%4];"
                             : "=r"(b1[0]), "=r"(b1[1]), "=r"(b1[2]), "=r"(b1[3])
                             : "r"(Bb + (wn + 16) * TSTRIDE + b_off + ks * 32));
#pragma unroll
                for (int mf = 0; mf < 4; mf++) {
                    uint32_t a[4];
                    asm volatile("ldmatrix.sync.aligned.m8n8.x4.shared.b16 {%0,%1,%2,%3}, [%4];"
                                 : "=r"(a[0]), "=r"(a[1]), "=r"(a[2]), "=r"(a[3])
                                 : "r"(Ab + (wm + mf * 16) * TSTRIDE + a_off + ks * 32));
#pragma unroll
                    for (int nf = 0; nf < 4; nf++) {
                        uint32_t* bp = (nf < 2) ? &b0[(nf & 1) * 2] : &b1[(nf & 1) * 2];
                        asm volatile(
                            "mma.sync.aligned.m16n8k16.row.col.f32.bf16.bf16.f32 "
                            "{%0,%1,%2,%3}, {%4,%5,%6,%7}, {%8,%9}, {%0,%1,%2,%3};"
                            : "+f"(acc[mf][nf][0]), "+f"(acc[mf][nf][1]),
                              "+f"(acc[mf][nf][2]), "+f"(acc[mf][nf][3])
                            : "r"(a[0]), "r"(a[1]), "r"(a[2]), "r"(a[3]),
                              "r"(bp[0]), "r"(bp[1]));
                    }
                }
            }
        }
    }

    const int mrow = m0 + wm + (lane >> 2);
    const int ncol = n0 + wn + (lane & 3) * 2;
#pragma unroll
    for (int mf = 0; mf < 4; mf++)
#pragma unroll
        for (int nf = 0; nf < 4; nf++) {
            size_t base = (size_t)(mrow + mf * 16) * HH + ncol + nf * 8;
            *(float2*)&g_C[base]          = make_float2(acc[mf][nf][0], acc[mf][nf][1]);
            *(float2*)&g_C[base + 8 * HH] = make_float2(acc[mf][nf][2], acc[mf][nf][3]);
        }
}

// ---------------------------------------------------------------------------
__device__ __forceinline__ void grid_sync() {
    __threadfence();
    __syncthreads();
    if (threadIdx.x == 0) {
        unsigned gen = g_bar_gen;
        if (atomicAdd(&g_bar_cnt, 1u) == NBLK - 1) {
            g_bar_cnt = 0;
            __threadfence();
            g_bar_gen = gen + 1;
        } else {
            while (g_bar_gen == gen) __nanosleep(40);
        }
        __threadfence();
    }
    __syncthreads();
}

// ---------------------------------------------------------------------------
// Persistent recurrent kernel on tensor cores.
// 128 blocks = 4 j-tiles(256) x 32 h-tiles(32). R^T slice resident in smem.
// Per step: stage spikes bf16 -> mma (3 R-splits) -> partials -> sync ->
//           LIF (4 elems/thread, reg state) -> sync.
// ---------------------------------------------------------------------------
__global__ void __launch_bounds__(NTHR, 1)
rsnn_persistent(float* __restrict__ out) {
    extern __shared__ char dynsm[];
    const uint32_t smA = smem_u32(dynsm);            // [128 b][ASTR]
    const uint32_t smR = smA + 128 * ASTR;           // 3 x [32 h][ASTR]

    const int bid = blockIdx.x;
    const int jt = bid >> 5;            // 0..3
    const int ht = bid & 31;            // 0..31
    const int j0 = jt * JTS;
    const int h0 = ht * HTS;
    const int tid = threadIdx.x;
    const int wid = tid >> 5;
    const int lane = tid & 31;
    const int wm = (wid & 3) * 32;      // m(batch) base of warp tile
    const int wn = (wid >> 2) * 16;     // n(h) base within 32-h tile

    // ldmatrix lane address offsets (proven in phase-1 kernel)
    const uint32_t a_off = (uint32_t)(lane & 15) * ASTR + ((lane >> 4) << 4);
    const uint32_t b_off = (uint32_t)((lane & 7) + ((lane >> 4) << 3)) * ASTR +
                           (((lane >> 3) & 1) << 4);

    // Load resident R^T slice: 3 splits x [32 h][256 j]
    for (int i = tid; i < 3 * 32 * 32; i += NTHR) {
        int p = i >> 10;
        int r = (i >> 5) & 31;
        int seg = i & 31;
        uint4 v = __ldg(&((const uint4*)g_Rt[p])[((size_t)(h0 + r) * HH + j0) / 8 + seg]);
        uint32_t dst = smR + p * (32 * ASTR) + r * ASTR + seg * 16;
        asm volatile("st.shared.v4.b32 [%0], {%1,%2,%3,%4};"
                     :: "r"(dst), "r"(v.x), "r"(v.y), "r"(v.z), "r"(v.w) : "memory");
    }

    // LIF ownership: 4 consecutive h per thread
    const int e0 = (bid * NTHR + tid) * 4;
    const int bl = e0 >> 10;
    const int hl = e0 & 1023;
    float mem[4] = {0.f, 0.f, 0.f, 0.f};
    float spk[4] = {0.f, 0.f, 0.f, 0.f};

    for (int t = 0; t < TT; t++) {
        const __nv_bfloat16* __restrict__ sb = g_spkb[t & 1];

        // stage spike tile [128 b][256 j] bf16 into smA
        for (int i = tid; i < 4096; i += NTHR) {
            int row = i >> 5;
            int seg = i & 31;
            uint4 v = __ldcg(&((const uint4*)sb)[((size_t)row * HH + j0) / 8 + seg]);
            uint32_t dst = smA + row * ASTR + seg * 16;
            asm volatile("st.shared.v4.b32 [%0], {%1,%2,%3,%4};"
                         :: "r"(dst), "r"(v.x), "r"(v.y), "r"(v.z), "r"(v.w) : "memory");
        }
        __syncthreads();

        float acc[2][2][4];
#pragma unroll
        for (int a = 0; a < 2; a++)
#pragma unroll
            for (int b = 0; b < 2; b++)
#pragma unroll
                for (int c = 0; c < 4; c++) acc[a][b][c] = 0.0f;

#pragma unroll
        for (int p = 0; p < 3; p++) {
            uint32_t Bb = smR + p * (32 * ASTR);
#pragma unroll
            for (int ks = 0; ks < 16; ks++) {
                uint32_t bfr[4];
                asm volatile("ldmatrix.sync.aligned.m8n8.x4.shared.b16 {%0,%1,%2,%3}, [%4];"
                             : "=r"(bfr[0]), "=r"(bfr[1]), "=r"(bfr[2]), "=r"(bfr[3])
                             : "r"(Bb + wn * ASTR + b_off + ks * 32));
#pragma unroll
                for (int mf = 0; mf < 2; mf++) {
                    uint32_t a[4];
                    asm volatile("ldmatrix.sync.aligned.m8n8.x4.shared.b16 {%0,%1,%2,%3}, [%4];"
                                 : "=r"(a[0]), "=r"(a[1]), "=r"(a[2]), "=r"(a[3])
                                 : "r"(smA + (wm + mf * 16) * ASTR + a_off + ks * 32));
#pragma unroll
                    for (int nf = 0; nf < 2; nf++) {
                        asm volatile(
                            "mma.sync.aligned.m16n8k16.row.col.f32.bf16.bf16.f32 "
                            "{%0,%1,%2,%3}, {%4,%5,%6,%7}, {%8,%9}, {%0,%1,%2,%3};"
                            : "+f"(acc[mf][nf][0]), "+f"(acc[mf][nf][1]),
                              "+f"(acc[mf][nf][2]), "+f"(acc[mf][nf][3])
                            : "r"(a[0]), "r"(a[1]), "r"(a[2]), "r"(a[3]),
                              "r"(bfr[nf * 2]), "r"(bfr[nf * 2 + 1]));
                    }
                }
            }
        }

        // write partials: warp tile m32 x n16 at (wm, h0+wn)
        {
            const int mrow = wm + (lane >> 2);
            const int ncol = h0 + wn + (lane & 3) * 2;
#pragma unroll
            for (int mf = 0; mf < 2; mf++)
#pragma unroll
                for (int nf = 0; nf < 2; nf++) {
                    *(float2*)&g_part[jt][mrow + mf * 16][ncol + nf * 8] =
                        make_float2(acc[mf][nf][0], acc[mf][nf][1]);
                    *(float2*)&g_part[jt][mrow + mf * 16 + 8][ncol + nf * 8] =
                        make_float2(acc[mf][nf][2], acc[mf][nf][3]);
                }
        }
        grid_sync();

        // LIF phase: 4 owned elements (b = bl, h = hl..hl+3)
        {
            float4 cur = *(const float4*)&g_C[((size_t)bl * TT + t) * HH + hl];
            float c4[4] = {cur.x, cur.y, cur.z, cur.w};
#pragma unroll
            for (int q = 0; q < NJT; q++) {
                float4 pv = __ldcg((const float4*)&g_part[q][bl][hl]);
                c4[0] += pv.x; c4[1] += pv.y; c4[2] += pv.z; c4[3] += pv.w;
            }
            __nv_bfloat16* so = g_spkb[(t + 1) & 1];
#pragma unroll
            for (int i = 0; i < 4; i++) {
                mem[i] = __fadd_rn(__fmul_rn(__fmul_rn(mem[i], DECAY), 1.0f - spk[i]), c4[i]);
                spk[i] = (mem[i] >= 1.0f) ? 1.0f : 0.0f;
            }
            *(__nv_bfloat162*)&so[bl * HH + hl] =
                __nv_bfloat162(__float2bfloat16_rn(spk[0]), __float2bfloat16_rn(spk[1]));
            *(__nv_bfloat162*)&so[bl * HH + hl + 2] =
                __nv_bfloat162(__float2bfloat16_rn(spk[2]), __float2bfloat16_rn(spk[3]));
            if (hl < NS) {
                float* op = &out[((size_t)bl * TT + t) * NS + hl];
#pragma unroll
                for (int i = 0; i < 4; i++)
                    if (hl + i < NS) op[i] = spk[i];
            }
        }
        grid_sync();
    }
}

// ---------------------------------------------------------------------------
extern "C" void kernel_launch(void* const* d_in, const int* in_sizes, int n_in,
                              void* d_out, int out_size) {
    const float* x   = (const float*)d_in[0];
    const float* fc1 = (const float*)d_in[1];
    const float* rec = (const float*)d_in[2];
    float* out = (float*)d_out;

    const int smem_g = 6 * 128 * TSTRIDE;            // 61,440 B
    cudaFuncSetAttribute(gemm_tc_kernel,
                         cudaFuncAttributeMaxDynamicSharedMemorySize, smem_g);
    const int smem_p = 128 * ASTR + 3 * 32 * ASTR;   // 118,272 B
    cudaFuncSetAttribute(rsnn_persistent,
                         cudaFuncAttributeMaxDynamicSharedMemorySize, smem_p);

    init_kernel<<<(BB * HH + 255) / 256, 256>>>(out, out_size);
    split_x_kernel<<<(BB * TT * (KP / 2) + 255) / 256, 256>>>(x);
    split_w_kernel<<<(HH * (KP / 2) + 255) / 256, 256>>>(fc1);
    split_r_kernel<<<(HH * (HH / 2) + 255) / 256, 256>>>(rec);
    gemm_tc_kernel<<<4000, 256, smem_g>>>();
    rsnn_persistent<<<NBLK, NTHR, smem_p>>>(out);
}